// round 10
// baseline (speedup 1.0000x reference)
#include <cuda_runtime.h>
#include <cuda.h>
#include <cuda_fp16.h>
#include <math.h>
#include <cstdint>

// ---------------------------------------------------------------------------
// Problem constants (fixed by setup_inputs)
#define B_DIM 2048
#define D_DIM 768
#define P_DIM 16384

// Tile config (fp16 path)
#define MT 128
#define NT 256
#define KT 64                            // halves per K chunk (128 B rows)
#define KSTAGES (D_DIM / KT)             // 12
#define NSPLIT (P_DIM / NT)              // 64
#define NSTG 4                           // pipeline stages

#define A_STAGE_BYTES (MT * KT * 2)      // 16384
#define B_STAGE_BYTES (NT * KT * 2)      // 32768
#define STAGE_TX (A_STAGE_BYTES + B_STAGE_BYTES)

// SMEM layout (dynamic)
#define SM_BAR    0                      // 4 mbarriers
#define SM_MERGE  64                     // 4*128*12 = 6144 B
#define SM_A      8192                   // 4 * 16384
#define SM_B      (SM_A + NSTG * A_STAGE_BYTES)   // 73728
#define SMEM_TOTAL (SM_B + NSTG * B_STAGE_BYTES)  // 204800

// ---------------------------------------------------------------------------
// Device scratch (allocation-free rule: static __device__ arrays)
__device__ __align__(1024) __half g_qh[B_DIM * D_DIM];
__device__ __align__(1024) __half g_ph[P_DIM * D_DIM];
__device__ float g_starget[B_DIM];
__device__ float g_pmax[B_DIM * NSPLIT];
__device__ float g_psum[B_DIM * NSPLIT];
__device__ int   g_pcnt[B_DIM * NSPLIT];
__device__ float g_rowloss[B_DIM];

// ---------------------------------------------------------------------------
// PTX helpers (non-'a' instructions only)
__device__ __forceinline__ uint32_t smem_u32(const void* p) {
    uint32_t a;
    asm("{ .reg .u64 t; cvta.to.shared.u64 t, %1; cvt.u32.u64 %0, t; }"
        : "=r"(a) : "l"(p));
    return a;
}
__device__ __forceinline__ void mbar_init(uint32_t mbar, uint32_t cnt) {
    asm volatile("mbarrier.init.shared.b64 [%0], %1;" :: "r"(mbar), "r"(cnt) : "memory");
}
__device__ __forceinline__ void mbar_expect_tx(uint32_t mbar, uint32_t bytes) {
    asm volatile("mbarrier.arrive.expect_tx.shared.b64 _, [%0], %1;"
                 :: "r"(mbar), "r"(bytes) : "memory");
}
__device__ __forceinline__ void mbar_wait(uint32_t mbar, uint32_t parity) {
    asm volatile("{\n\t.reg .pred P;\n\tWL_%=:\n\t"
        "mbarrier.try_wait.parity.acquire.cta.shared::cta.b64 P, [%0], %1, 0x989680;\n\t"
        "@P bra.uni WD_%=;\n\tbra.uni WL_%=;\n\tWD_%=:\n\t}"
        :: "r"(mbar), "r"(parity) : "memory");
}
__device__ __forceinline__ void tma_load_2d(uint32_t dst, const CUtensorMap* map,
                                            int x, int y, uint32_t mbar) {
    asm volatile("cp.async.bulk.tensor.2d.shared::cta.global.tile.mbarrier::complete_tx::bytes "
                 "[%0], [%1, {%2, %3}], [%4];"
                 :: "r"(dst), "l"(map), "r"(x), "r"(y), "r"(mbar) : "memory");
}
__device__ __forceinline__ void fence_async() {
    asm volatile("fence.proxy.async.shared::cta;" ::: "memory");
}
__device__ __forceinline__ void ldsm_x4(uint32_t& r0, uint32_t& r1,
                                        uint32_t& r2, uint32_t& r3, uint32_t a) {
    asm volatile("ldmatrix.sync.aligned.m8n8.x4.shared.b16 {%0,%1,%2,%3}, [%4];"
                 : "=r"(r0), "=r"(r1), "=r"(r2), "=r"(r3) : "r"(a));
}
// m16n8k16 fp16 warp MMA, fp32 accumulate (HMMA tensor path; plain sm_103 OK)
__device__ __forceinline__ void mma16(float* c, const uint32_t* a,
                                      uint32_t b0, uint32_t b1) {
    asm("mma.sync.aligned.m16n8k16.row.col.f32.f16.f16.f32 "
        "{%0,%1,%2,%3}, {%4,%5,%6,%7}, {%8,%9}, {%0,%1,%2,%3};"
        : "+f"(c[0]), "+f"(c[1]), "+f"(c[2]), "+f"(c[3])
        : "r"(a[0]), "r"(a[1]), "r"(a[2]), "r"(a[3]), "r"(b0), "r"(b1));
}

// ---------------------------------------------------------------------------
// Kernel 0: fp32 -> fp16 copies of q and p (one float4 -> 4 halves per thread)
#define QF4 (B_DIM * D_DIM / 4)
#define PF4 (P_DIM * D_DIM / 4)
__global__ void convert_kernel(const float* __restrict__ q,
                               const float* __restrict__ p) {
    int i = blockIdx.x * blockDim.x + threadIdx.x;
    if (i < QF4) {
        float4 v = ((const float4*)q)[i];
        __half2* o = (__half2*)(g_qh + (size_t)i * 4);
        o[0] = __float22half2_rn(make_float2(v.x, v.y));
        o[1] = __float22half2_rn(make_float2(v.z, v.w));
    } else if (i < QF4 + PF4) {
        int j = i - QF4;
        float4 v = ((const float4*)p)[j];
        __half2* o = (__half2*)(g_ph + (size_t)j * 4);
        o[0] = __float22half2_rn(make_float2(v.x, v.y));
        o[1] = __float22half2_rn(make_float2(v.z, v.w));
    }
}

// ---------------------------------------------------------------------------
// Kernel 1: s_target[b] = dot(q[b], p[b * np])   (exact fp32)
__global__ void target_kernel(const float* __restrict__ q,
                              const float* __restrict__ p, int np) {
    int b    = blockIdx.x * 8 + (threadIdx.x >> 5);
    int lane = threadIdx.x & 31;
    const float4* qr = (const float4*)(q + (size_t)b * D_DIM);
    const float4* pr = (const float4*)(p + (size_t)b * np * D_DIM);
    float s = 0.f;
    #pragma unroll
    for (int k = lane; k < D_DIM / 4; k += 32) {
        float4 a = qr[k], c = pr[k];
        s += a.x * c.x + a.y * c.y + a.z * c.z + a.w * c.w;
    }
    #pragma unroll
    for (int m = 16; m; m >>= 1) s += __shfl_xor_sync(0xffffffffu, s, m);
    if (lane == 0) g_starget[b] = s;
}

// ---------------------------------------------------------------------------
// Kernel 2: fp16 warp-MMA GEMM (CTA 128x256, warp 64x64) + fused epilogue
__global__ void __launch_bounds__(256, 1)
fused_mma_kernel(const __grid_constant__ CUtensorMap tmap_a,
                 const __grid_constant__ CUtensorMap tmap_b) {
    extern __shared__ char smem[];
    const uint32_t sbase = smem_u32(smem);
    const int tid  = threadIdx.x;
    const int wid  = tid >> 5;
    const int lane = tid & 31;
    const int g    = lane >> 2;            // 0..7
    const int t    = lane & 3;             // 0..3
    const int wm   = wid & 1;              // warp row (64 rows)
    const int wn   = wid >> 1;             // warp col (64 cols), 0..3

    const int m0 = blockIdx.y * MT;
    const int n0 = blockIdx.x * NT;

    if (tid == 0) {
        #pragma unroll
        for (int i = 0; i < NSTG; ++i) mbar_init(sbase + SM_BAR + 8 * i, 1);
        fence_async();
    }
    __syncthreads();

    if (tid == 0) {
        #pragma unroll
        for (int st = 0; st < NSTG; ++st) {
            mbar_expect_tx(sbase + SM_BAR + 8 * st, STAGE_TX);
            tma_load_2d(sbase + SM_A + st * A_STAGE_BYTES, &tmap_a, st * KT, m0,
                        sbase + SM_BAR + 8 * st);
            tma_load_2d(sbase + SM_B + st * B_STAGE_BYTES, &tmap_b, st * KT, n0,
                        sbase + SM_BAR + 8 * st);
        }
    }

    float c[4][8][4];
    #pragma unroll
    for (int mt = 0; mt < 4; ++mt)
        #pragma unroll
        for (int nt = 0; nt < 8; ++nt)
            #pragma unroll
            for (int k = 0; k < 4; ++k) c[mt][nt][k] = 0.f;

    // ldmatrix lane-address components (row stride 128 B, SW128 swizzle:
    // physical 16B chunk = chunk ^ (row & 7))
    const int a_row_l = (lane & 7) + (lane & 8);            // + mt*16 + wm*64
    const int a_kc_l  = (lane >> 4) & 1;                    // 16B chunk within k16
    const int b_row_l = (lane & 7) + ((lane >> 4) & 1) * 8; // + nt2*16 + wn*64
    const int b_kc_l  = (lane >> 3) & 1;

    int slot = 0, parity = 0;
    for (int s = 0; s < KSTAGES; ++s) {
        mbar_wait(sbase + SM_BAR + 8 * slot, parity);
        const uint32_t As = sbase + SM_A + slot * A_STAGE_BYTES;
        const uint32_t Bs = sbase + SM_B + slot * B_STAGE_BYTES;

        #pragma unroll
        for (int ks = 0; ks < 4; ++ks) {                 // 4 x k16 per stage
            uint32_t a[4][4], b[8][2];
            #pragma unroll
            for (int mt = 0; mt < 4; ++mt) {
                int row = wm * 64 + mt * 16 + a_row_l;
                int chk = (ks * 2 + a_kc_l) ^ (row & 7);
                ldsm_x4(a[mt][0], a[mt][1], a[mt][2], a[mt][3],
                        As + row * 128 + chk * 16);
            }
            #pragma unroll
            for (int n2 = 0; n2 < 4; ++n2) {
                int row = wn * 64 + n2 * 16 + b_row_l;
                int chk = (ks * 2 + b_kc_l) ^ (row & 7);
                ldsm_x4(b[n2 * 2][0], b[n2 * 2][1], b[n2 * 2 + 1][0], b[n2 * 2 + 1][1],
                        Bs + row * 128 + chk * 16);
            }
            #pragma unroll
            for (int mt = 0; mt < 4; ++mt)
                #pragma unroll
                for (int nt = 0; nt < 8; ++nt)
                    mma16(c[mt][nt], a[mt], b[nt][0], b[nt][1]);
        }

        __syncthreads();                                  // slot fully consumed
        if (tid == 0 && s + NSTG < KSTAGES) {
            mbar_expect_tx(sbase + SM_BAR + 8 * slot, STAGE_TX);
            tma_load_2d(sbase + SM_A + slot * A_STAGE_BYTES, &tmap_a,
                        (s + NSTG) * KT, m0, sbase + SM_BAR + 8 * slot);
            tma_load_2d(sbase + SM_B + slot * B_STAGE_BYTES, &tmap_b,
                        (s + NSTG) * KT, n0, sbase + SM_BAR + 8 * slot);
        }
        if (++slot == NSTG) { slot = 0; parity ^= 1; }
    }

    // ---------------- epilogue ---------------------------------------------
    float* mg_max = (float*)(smem + SM_MERGE);            // [4][128]
    float* mg_sum = mg_max + 4 * 128;
    int*   mg_cnt = (int*)(mg_sum + 4 * 128);

    #pragma unroll
    for (int mt = 0; mt < 4; ++mt) {
        #pragma unroll
        for (int half = 0; half < 2; ++half) {
            const int rloc = wm * 64 + mt * 16 + half * 8 + g;
            const int row  = m0 + rloc;
            const float st = g_starget[row];
            const int tcol = row * 8;                     // n_passages = 8

            float vmax = -INFINITY;
            #pragma unroll
            for (int nt = 0; nt < 8; ++nt) {
                vmax = fmaxf(vmax, c[mt][nt][half * 2]);
                vmax = fmaxf(vmax, c[mt][nt][half * 2 + 1]);
            }
            float vsum = 0.f;
            int   vcnt = 0;
            #pragma unroll
            for (int nt = 0; nt < 8; ++nt) {
                const int col = n0 + wn * 64 + nt * 8 + t * 2;
                float v0 = c[mt][nt][half * 2];
                float v1 = c[mt][nt][half * 2 + 1];
                vsum += __expf(v0 - vmax) + __expf(v1 - vmax);
                vcnt += (v0 > st) && (col != tcol);
                vcnt += (v1 > st) && (col + 1 != tcol);
            }
            #pragma unroll
            for (int d = 1; d < 4; d <<= 1) {
                float om = __shfl_xor_sync(0xffffffffu, vmax, d);
                float os = __shfl_xor_sync(0xffffffffu, vsum, d);
                int   oc = __shfl_xor_sync(0xffffffffu, vcnt, d);
                float nm = fmaxf(vmax, om);
                vsum = vsum * __expf(vmax - nm) + os * __expf(om - nm);
                vmax = nm;
                vcnt += oc;
            }
            if (t == 0) {
                mg_max[wn * 128 + rloc] = vmax;
                mg_sum[wn * 128 + rloc] = vsum;
                mg_cnt[wn * 128 + rloc] = vcnt;
            }
        }
    }
    __syncthreads();

    if (tid < 128) {
        const int rloc = tid;
        const int row  = m0 + rloc;
        float M = mg_max[rloc];
        #pragma unroll
        for (int w = 1; w < 4; ++w) M = fmaxf(M, mg_max[w * 128 + rloc]);
        float S = 0.f;
        int   C = 0;
        #pragma unroll
        for (int w = 0; w < 4; ++w) {
            S += mg_sum[w * 128 + rloc] * __expf(mg_max[w * 128 + rloc] - M);
            C += mg_cnt[w * 128 + rloc];
        }
        const int split = blockIdx.x;
        g_pmax[row * NSPLIT + split] = M;
        g_psum[row * NSPLIT + split] = S;
        g_pcnt[row * NSPLIT + split] = C;
    }
}

// ---------------------------------------------------------------------------
// Kernel 3: one warp per row — merge 64 split partials, weight, store rowloss
__global__ void rowloss_kernel() {
    const int row  = blockIdx.x * 8 + (threadIdx.x >> 5);
    const int lane = threadIdx.x & 31;

    // Each lane owns 2 splits (coalesced: lane, lane+32)
    float m0 = g_pmax[row * NSPLIT + lane];
    float m1 = g_pmax[row * NSPLIT + lane + 32];
    float s0 = g_psum[row * NSPLIT + lane];
    float s1 = g_psum[row * NSPLIT + lane + 32];
    int   c  = g_pcnt[row * NSPLIT + lane] + g_pcnt[row * NSPLIT + lane + 32];

    float M = fmaxf(m0, m1);
    float S = s0 * __expf(m0 - M) + s1 * __expf(m1 - M);

    #pragma unroll
    for (int d = 16; d; d >>= 1) {
        float om = __shfl_xor_sync(0xffffffffu, M, d);
        float os = __shfl_xor_sync(0xffffffffu, S, d);
        int   oc = __shfl_xor_sync(0xffffffffu, c, d);
        float nm = fmaxf(M, om);
        S = S * __expf(M - nm) + os * __expf(om - nm);
        M = nm;
        c += oc;
    }

    if (lane == 0) {
        float lse = M + logf(S);
        float raw = lse - g_starget[row];
        float d   = (float)c - 1.0f;                        // OPTIMAL_RANK = 1
        float w   = 1.0f + 2.6f * expf(-(d * d) * (1.0f / 6.48f)); // 2*1.8^2
        g_rowloss[row] = raw * w;
    }
}

// ---------------------------------------------------------------------------
// Kernel 4: reduce 2048 row losses -> mean (single small block-tree)
__global__ void reduce_kernel(float* __restrict__ out) {
    __shared__ float red[1024];
    const int t = threadIdx.x;
    red[t] = g_rowloss[t] + g_rowloss[t + 1024];
    __syncthreads();
    #pragma unroll
    for (int s = 512; s > 32; s >>= 1) {
        if (t < s) red[t] += red[t + s];
        __syncthreads();
    }
    if (t < 32) {
        float v = red[t] + red[t + 32];
        #pragma unroll
        for (int d = 16; d; d >>= 1) v += __shfl_xor_sync(0xffffffffu, v, d);
        if (t == 0) out[0] = v / (float)B_DIM;
    }
}

// ---------------------------------------------------------------------------
typedef CUresult (*EncodeTiledFn)(
    CUtensorMap*, CUtensorMapDataType, cuuint32_t, void*,
    const cuuint64_t*, const cuuint64_t*, const cuuint32_t*, const cuuint32_t*,
    CUtensorMapInterleave, CUtensorMapSwizzle, CUtensorMapL2promotion,
    CUtensorMapFloatOOBfill);

static void encode_map_f16(EncodeTiledFn fn, CUtensorMap* m, void* ptr,
                           uint64_t rows, uint32_t box_rows) {
    cuuint64_t dims[2]    = {(cuuint64_t)D_DIM, (cuuint64_t)rows};
    cuuint64_t strides[1] = {(cuuint64_t)D_DIM * sizeof(__half)};
    cuuint32_t box[2]     = {KT, box_rows};     // 64 halves = 128 B inner box
    cuuint32_t estr[2]    = {1, 1};
    fn(m, CU_TENSOR_MAP_DATA_TYPE_FLOAT16, 2, ptr, dims, strides, box, estr,
       CU_TENSOR_MAP_INTERLEAVE_NONE, CU_TENSOR_MAP_SWIZZLE_128B,
       CU_TENSOR_MAP_L2_PROMOTION_L2_128B, CU_TENSOR_MAP_FLOAT_OOB_FILL_NONE);
}

extern "C" void kernel_launch(void* const* d_in, const int* in_sizes, int n_in,
                              void* d_out, int out_size) {
    const float* q = (const float*)d_in[0];
    const float* p = (const float*)d_in[1];
    int np = in_sizes[1] / in_sizes[0];                    // = 8

    void* sym = nullptr;
    cudaDriverEntryPointQueryResult qres;
    cudaGetDriverEntryPoint("cuTensorMapEncodeTiled", &sym,
                            cudaEnableDefault, &qres);
    EncodeTiledFn enc = (EncodeTiledFn)sym;

    void *qh_ptr = nullptr, *ph_ptr = nullptr;
    cudaGetSymbolAddress(&qh_ptr, g_qh);
    cudaGetSymbolAddress(&ph_ptr, g_ph);

    CUtensorMap tmap_a, tmap_b;
    encode_map_f16(enc, &tmap_a, qh_ptr, B_DIM, MT);
    encode_map_f16(enc, &tmap_b, ph_ptr, P_DIM, NT);

    cudaFuncSetAttribute(fused_mma_kernel,
                         cudaFuncAttributeMaxDynamicSharedMemorySize, SMEM_TOTAL);

    convert_kernel<<<(QF4 + PF4 + 255) / 256, 256>>>(q, p);
    target_kernel<<<B_DIM / 8, 256>>>(q, p, np);
    fused_mma_kernel<<<dim3(P_DIM / NT, B_DIM / MT), 256, SMEM_TOTAL>>>(tmap_a, tmap_b);
    rowloss_kernel<<<B_DIM / 8, 256>>>();
    reduce_kernel<<<1, 1024>>>((float*)d_out);
}

// round 11
// speedup vs baseline: 1.0111x; 1.0111x over previous
#include <cuda_runtime.h>
#include <cuda.h>
#include <cuda_fp16.h>
#include <math.h>
#include <cstdint>

// ---------------------------------------------------------------------------
// Problem constants (fixed by setup_inputs)
#define B_DIM 2048
#define D_DIM 768
#define P_DIM 16384

// Tile config (fp16 path)
#define MT 128
#define NT 256
#define KT 64                            // halves per K chunk (128 B rows)
#define KSTAGES (D_DIM / KT)             // 12
#define NSPLIT (P_DIM / NT)              // 64
#define NTILES_M (B_DIM / MT)            // 16
#define NUM_TILES (NSPLIT * NTILES_M)    // 1024
#define NSTG 4                           // pipeline stages

#define A_STAGE_BYTES (MT * KT * 2)      // 16384
#define B_STAGE_BYTES (NT * KT * 2)      // 32768
#define STAGE_TX (A_STAGE_BYTES + B_STAGE_BYTES)

// SMEM layout (dynamic)
#define SM_BAR    0                      // 4 mbarriers
#define SM_MERGE  64                     // 4*128*12 = 6144 B
#define SM_A      8192                   // 4 * 16384
#define SM_B      (SM_A + NSTG * A_STAGE_BYTES)   // 73728
#define SMEM_TOTAL (SM_B + NSTG * B_STAGE_BYTES)  // 204800

// ---------------------------------------------------------------------------
// Device scratch (allocation-free rule: static __device__ arrays)
__device__ __align__(1024) __half g_qh[B_DIM * D_DIM];
__device__ __align__(1024) __half g_ph[P_DIM * D_DIM];
__device__ float g_starget[B_DIM];
__device__ float g_pmax[B_DIM * NSPLIT];
__device__ float g_psum[B_DIM * NSPLIT];
__device__ int   g_pcnt[B_DIM * NSPLIT];
__device__ float g_rowloss[B_DIM];

// ---------------------------------------------------------------------------
// PTX helpers (non-'a' instructions only)
__device__ __forceinline__ uint32_t smem_u32(const void* p) {
    uint32_t a;
    asm("{ .reg .u64 t; cvta.to.shared.u64 t, %1; cvt.u32.u64 %0, t; }"
        : "=r"(a) : "l"(p));
    return a;
}
__device__ __forceinline__ void mbar_init(uint32_t mbar, uint32_t cnt) {
    asm volatile("mbarrier.init.shared.b64 [%0], %1;" :: "r"(mbar), "r"(cnt) : "memory");
}
__device__ __forceinline__ void mbar_expect_tx(uint32_t mbar, uint32_t bytes) {
    asm volatile("mbarrier.arrive.expect_tx.shared.b64 _, [%0], %1;"
                 :: "r"(mbar), "r"(bytes) : "memory");
}
__device__ __forceinline__ void mbar_wait(uint32_t mbar, uint32_t parity) {
    asm volatile("{\n\t.reg .pred P;\n\tWL_%=:\n\t"
        "mbarrier.try_wait.parity.acquire.cta.shared::cta.b64 P, [%0], %1, 0x989680;\n\t"
        "@P bra.uni WD_%=;\n\tbra.uni WL_%=;\n\tWD_%=:\n\t}"
        :: "r"(mbar), "r"(parity) : "memory");
}
__device__ __forceinline__ void tma_load_2d(uint32_t dst, const CUtensorMap* map,
                                            int x, int y, uint32_t mbar) {
    asm volatile("cp.async.bulk.tensor.2d.shared::cta.global.tile.mbarrier::complete_tx::bytes "
                 "[%0], [%1, {%2, %3}], [%4];"
                 :: "r"(dst), "l"(map), "r"(x), "r"(y), "r"(mbar) : "memory");
}
__device__ __forceinline__ void fence_async() {
    asm volatile("fence.proxy.async.shared::cta;" ::: "memory");
}
__device__ __forceinline__ void ldsm_x4(uint32_t& r0, uint32_t& r1,
                                        uint32_t& r2, uint32_t& r3, uint32_t a) {
    asm volatile("ldmatrix.sync.aligned.m8n8.x4.shared.b16 {%0,%1,%2,%3}, [%4];"
                 : "=r"(r0), "=r"(r1), "=r"(r2), "=r"(r3) : "r"(a));
}
// m16n8k16 fp16 warp MMA, fp32 accumulate (HMMA tensor path; plain sm_103 OK)
__device__ __forceinline__ void mma16(float* c, const uint32_t* a,
                                      uint32_t b0, uint32_t b1) {
    asm("mma.sync.aligned.m16n8k16.row.col.f32.f16.f16.f32 "
        "{%0,%1,%2,%3}, {%4,%5,%6,%7}, {%8,%9}, {%0,%1,%2,%3};"
        : "+f"(c[0]), "+f"(c[1]), "+f"(c[2]), "+f"(c[3])
        : "r"(a[0]), "r"(a[1]), "r"(a[2]), "r"(a[3]), "r"(b0), "r"(b1));
}

// ---------------------------------------------------------------------------
// Kernel 0: fp32 -> fp16 copies of q and p (one float4 -> 4 halves per thread)
#define QF4 (B_DIM * D_DIM / 4)
#define PF4 (P_DIM * D_DIM / 4)
__global__ void convert_kernel(const float* __restrict__ q,
                               const float* __restrict__ p) {
    int i = blockIdx.x * blockDim.x + threadIdx.x;
    if (i < QF4) {
        float4 v = ((const float4*)q)[i];
        __half2* o = (__half2*)(g_qh + (size_t)i * 4);
        o[0] = __float22half2_rn(make_float2(v.x, v.y));
        o[1] = __float22half2_rn(make_float2(v.z, v.w));
    } else if (i < QF4 + PF4) {
        int j = i - QF4;
        float4 v = ((const float4*)p)[j];
        __half2* o = (__half2*)(g_ph + (size_t)j * 4);
        o[0] = __float22half2_rn(make_float2(v.x, v.y));
        o[1] = __float22half2_rn(make_float2(v.z, v.w));
    }
}

// ---------------------------------------------------------------------------
// Kernel 1: s_target[b] = dot(q[b], p[b * np])   (exact fp32)
__global__ void target_kernel(const float* __restrict__ q,
                              const float* __restrict__ p, int np) {
    int b    = blockIdx.x * 8 + (threadIdx.x >> 5);
    int lane = threadIdx.x & 31;
    const float4* qr = (const float4*)(q + (size_t)b * D_DIM);
    const float4* pr = (const float4*)(p + (size_t)b * np * D_DIM);
    float s = 0.f;
    #pragma unroll
    for (int k = lane; k < D_DIM / 4; k += 32) {
        float4 a = qr[k], c = pr[k];
        s += a.x * c.x + a.y * c.y + a.z * c.z + a.w * c.w;
    }
    #pragma unroll
    for (int m = 16; m; m >>= 1) s += __shfl_xor_sync(0xffffffffu, s, m);
    if (lane == 0) g_starget[b] = s;
}

// ---------------------------------------------------------------------------
// Kernel 2: PERSISTENT fp16 warp-MMA GEMM. Each CTA processes tiles
// T = bid, bid+grid, ... as one continuous stage stream; TMA prefetch of
// stage g+NSTG (possibly next tile) is issued right after stage g is
// consumed, so the pipeline never drains across tile boundaries/epilogues.
__global__ void __launch_bounds__(256, 1)
fused_mma_kernel(const __grid_constant__ CUtensorMap tmap_a,
                 const __grid_constant__ CUtensorMap tmap_b) {
    extern __shared__ char smem[];
    const uint32_t sbase = smem_u32(smem);
    const int tid  = threadIdx.x;
    const int wid  = tid >> 5;
    const int lane = tid & 31;
    const int g    = lane >> 2;            // 0..7
    const int t    = lane & 3;             // 0..3
    const int wm   = wid & 1;              // warp row (64 rows)
    const int wn   = wid >> 1;             // warp col (64 cols), 0..3
    const int bid  = blockIdx.x;
    const int grid = gridDim.x;

    const int ntiles = (bid < NUM_TILES) ? ((NUM_TILES - 1 - bid) / grid + 1) : 0;
    const int total  = ntiles * KSTAGES;

    if (tid == 0) {
        #pragma unroll
        for (int i = 0; i < NSTG; ++i) mbar_init(sbase + SM_BAR + 8 * i, 1);
        fence_async();
    }
    __syncthreads();

    // Current-tile state (all threads)
    int Tt = bid;
    int m0 = (Tt >> 6) * MT;
    int n0 = (Tt & 63) * NT;

    // Prologue: fill pipeline with stages 0..NSTG-1 of tile 0 (NSTG < KSTAGES)
    if (tid == 0 && total > 0) {
        #pragma unroll
        for (int st = 0; st < NSTG; ++st) {
            mbar_expect_tx(sbase + SM_BAR + 8 * st, STAGE_TX);
            tma_load_2d(sbase + SM_A + st * A_STAGE_BYTES, &tmap_a, st * KT, m0,
                        sbase + SM_BAR + 8 * st);
            tma_load_2d(sbase + SM_B + st * B_STAGE_BYTES, &tmap_b, st * KT, n0,
                        sbase + SM_BAR + 8 * st);
        }
    }

    // Prefetch cursor (coords of stage g+NSTG); uniform across threads
    int kp = NSTG, Tp = bid;
    int issued = NSTG;

    float c[4][8][4];
    #pragma unroll
    for (int mt = 0; mt < 4; ++mt)
        #pragma unroll
        for (int nt = 0; nt < 8; ++nt)
            #pragma unroll
            for (int k = 0; k < 4; ++k) c[mt][nt][k] = 0.f;

    // ldmatrix lane-address components (row stride 128 B, SW128 swizzle:
    // physical 16B chunk = chunk ^ (row & 7))
    const int a_row_l = (lane & 7) + (lane & 8);            // + mt*16 + wm*64
    const int a_kc_l  = (lane >> 4) & 1;                    // 16B chunk within k16
    const int b_row_l = (lane & 7) + ((lane >> 4) & 1) * 8; // + nt2*16 + wn*64
    const int b_kc_l  = (lane >> 3) & 1;

    float* mg_max = (float*)(smem + SM_MERGE);              // [4][128]
    float* mg_sum = mg_max + 4 * 128;
    int*   mg_cnt = (int*)(mg_sum + 4 * 128);

    int slot = 0, parity = 0, kcur = 0;
    for (int gs = 0; gs < total; ++gs) {
        mbar_wait(sbase + SM_BAR + 8 * slot, parity);
        const uint32_t As = sbase + SM_A + slot * A_STAGE_BYTES;
        const uint32_t Bs = sbase + SM_B + slot * B_STAGE_BYTES;

        #pragma unroll
        for (int ks = 0; ks < 4; ++ks) {                 // 4 x k16 per stage
            uint32_t a[4][4], b[8][2];
            #pragma unroll
            for (int mt = 0; mt < 4; ++mt) {
                int row = wm * 64 + mt * 16 + a_row_l;
                int chk = (ks * 2 + a_kc_l) ^ (row & 7);
                ldsm_x4(a[mt][0], a[mt][1], a[mt][2], a[mt][3],
                        As + row * 128 + chk * 16);
            }
            #pragma unroll
            for (int n2 = 0; n2 < 4; ++n2) {
                int row = wn * 64 + n2 * 16 + b_row_l;
                int chk = (ks * 2 + b_kc_l) ^ (row & 7);
                ldsm_x4(b[n2 * 2][0], b[n2 * 2][1], b[n2 * 2 + 1][0], b[n2 * 2 + 1][1],
                        Bs + row * 128 + chk * 16);
            }
            #pragma unroll
            for (int mt = 0; mt < 4; ++mt)
                #pragma unroll
                for (int nt = 0; nt < 8; ++nt)
                    mma16(c[mt][nt], a[mt], b[nt][0], b[nt][1]);
        }

        __syncthreads();                                  // slot fully consumed

        // Refill freed slot with stage gs+NSTG (crosses tile boundaries)
        if (issued < total) {
            if (tid == 0) {
                const int pm0 = (Tp >> 6) * MT;
                const int pn0 = (Tp & 63) * NT;
                mbar_expect_tx(sbase + SM_BAR + 8 * slot, STAGE_TX);
                tma_load_2d(sbase + SM_A + slot * A_STAGE_BYTES, &tmap_a,
                            kp * KT, pm0, sbase + SM_BAR + 8 * slot);
                tma_load_2d(sbase + SM_B + slot * B_STAGE_BYTES, &tmap_b,
                            kp * KT, pn0, sbase + SM_BAR + 8 * slot);
            }
            ++issued;
            if (++kp == KSTAGES) { kp = 0; Tp += grid; }
        }

        // Tile finished? -> epilogue (TMA prefetch continues in background)
        if (++kcur == KSTAGES) {
            #pragma unroll
            for (int mt = 0; mt < 4; ++mt) {
                #pragma unroll
                for (int half = 0; half < 2; ++half) {
                    const int rloc = wm * 64 + mt * 16 + half * 8 + g;
                    const int row  = m0 + rloc;
                    const float st = g_starget[row];
                    const int tcol = row * 8;             // n_passages = 8

                    float vmax = -INFINITY;
                    #pragma unroll
                    for (int nt = 0; nt < 8; ++nt) {
                        vmax = fmaxf(vmax, c[mt][nt][half * 2]);
                        vmax = fmaxf(vmax, c[mt][nt][half * 2 + 1]);
                    }
                    float vsum = 0.f;
                    int   vcnt = 0;
                    #pragma unroll
                    for (int nt = 0; nt < 8; ++nt) {
                        const int col = n0 + wn * 64 + nt * 8 + t * 2;
                        float v0 = c[mt][nt][half * 2];
                        float v1 = c[mt][nt][half * 2 + 1];
                        vsum += __expf(v0 - vmax) + __expf(v1 - vmax);
                        vcnt += (v0 > st) && (col != tcol);
                        vcnt += (v1 > st) && (col + 1 != tcol);
                    }
                    #pragma unroll
                    for (int d = 1; d < 4; d <<= 1) {
                        float om = __shfl_xor_sync(0xffffffffu, vmax, d);
                        float os = __shfl_xor_sync(0xffffffffu, vsum, d);
                        int   oc = __shfl_xor_sync(0xffffffffu, vcnt, d);
                        float nm = fmaxf(vmax, om);
                        vsum = vsum * __expf(vmax - nm) + os * __expf(om - nm);
                        vmax = nm;
                        vcnt += oc;
                    }
                    if (t == 0) {
                        mg_max[wn * 128 + rloc] = vmax;
                        mg_sum[wn * 128 + rloc] = vsum;
                        mg_cnt[wn * 128 + rloc] = vcnt;
                    }
                }
            }
            __syncthreads();

            if (tid < 128) {
                const int rloc = tid;
                const int row  = m0 + rloc;
                float M = mg_max[rloc];
                #pragma unroll
                for (int w = 1; w < 4; ++w) M = fmaxf(M, mg_max[w * 128 + rloc]);
                float S = 0.f;
                int   C = 0;
                #pragma unroll
                for (int w = 0; w < 4; ++w) {
                    S += mg_sum[w * 128 + rloc] * __expf(mg_max[w * 128 + rloc] - M);
                    C += mg_cnt[w * 128 + rloc];
                }
                const int split = Tt & 63;
                g_pmax[row * NSPLIT + split] = M;
                g_psum[row * NSPLIT + split] = S;
                g_pcnt[row * NSPLIT + split] = C;
            }

            // reset accumulators + advance tile
            #pragma unroll
            for (int mt = 0; mt < 4; ++mt)
                #pragma unroll
                for (int nt = 0; nt < 8; ++nt)
                    #pragma unroll
                    for (int k = 0; k < 4; ++k) c[mt][nt][k] = 0.f;
            kcur = 0;
            Tt += grid;
            m0 = (Tt >> 6) * MT;
            n0 = (Tt & 63) * NT;
        }

        if (++slot == NSTG) { slot = 0; parity ^= 1; }
    }
}

// ---------------------------------------------------------------------------
// Kernel 3: one warp per row — merge 64 split partials, weight, store rowloss
__global__ void rowloss_kernel() {
    const int row  = blockIdx.x * 8 + (threadIdx.x >> 5);
    const int lane = threadIdx.x & 31;

    float m0 = g_pmax[row * NSPLIT + lane];
    float m1 = g_pmax[row * NSPLIT + lane + 32];
    float s0 = g_psum[row * NSPLIT + lane];
    float s1 = g_psum[row * NSPLIT + lane + 32];
    int   c  = g_pcnt[row * NSPLIT + lane] + g_pcnt[row * NSPLIT + lane + 32];

    float M = fmaxf(m0, m1);
    float S = s0 * __expf(m0 - M) + s1 * __expf(m1 - M);

    #pragma unroll
    for (int d = 16; d; d >>= 1) {
        float om = __shfl_xor_sync(0xffffffffu, M, d);
        float os = __shfl_xor_sync(0xffffffffu, S, d);
        int   oc = __shfl_xor_sync(0xffffffffu, c, d);
        float nm = fmaxf(M, om);
        S = S * __expf(M - nm) + os * __expf(om - nm);
        M = nm;
        c += oc;
    }

    if (lane == 0) {
        float lse = M + logf(S);
        float raw = lse - g_starget[row];
        float d   = (float)c - 1.0f;                        // OPTIMAL_RANK = 1
        float w   = 1.0f + 2.6f * expf(-(d * d) * (1.0f / 6.48f)); // 2*1.8^2
        g_rowloss[row] = raw * w;
    }
}

// ---------------------------------------------------------------------------
// Kernel 4: reduce 2048 row losses -> mean (single small block-tree)
__global__ void reduce_kernel(float* __restrict__ out) {
    __shared__ float red[1024];
    const int t = threadIdx.x;
    red[t] = g_rowloss[t] + g_rowloss[t + 1024];
    __syncthreads();
    #pragma unroll
    for (int s = 512; s > 32; s >>= 1) {
        if (t < s) red[t] += red[t + s];
        __syncthreads();
    }
    if (t < 32) {
        float v = red[t] + red[t + 32];
        #pragma unroll
        for (int d = 16; d; d >>= 1) v += __shfl_xor_sync(0xffffffffu, v, d);
        if (t == 0) out[0] = v / (float)B_DIM;
    }
}

// ---------------------------------------------------------------------------
typedef CUresult (*EncodeTiledFn)(
    CUtensorMap*, CUtensorMapDataType, cuuint32_t, void*,
    const cuuint64_t*, const cuuint64_t*, const cuuint32_t*, const cuuint32_t*,
    CUtensorMapInterleave, CUtensorMapSwizzle, CUtensorMapL2promotion,
    CUtensorMapFloatOOBfill);

static void encode_map_f16(EncodeTiledFn fn, CUtensorMap* m, void* ptr,
                           uint64_t rows, uint32_t box_rows) {
    cuuint64_t dims[2]    = {(cuuint64_t)D_DIM, (cuuint64_t)rows};
    cuuint64_t strides[1] = {(cuuint64_t)D_DIM * sizeof(__half)};
    cuuint32_t box[2]     = {KT, box_rows};     // 64 halves = 128 B inner box
    cuuint32_t estr[2]    = {1, 1};
    fn(m, CU_TENSOR_MAP_DATA_TYPE_FLOAT16, 2, ptr, dims, strides, box, estr,
       CU_TENSOR_MAP_INTERLEAVE_NONE, CU_TENSOR_MAP_SWIZZLE_128B,
       CU_TENSOR_MAP_L2_PROMOTION_L2_128B, CU_TENSOR_MAP_FLOAT_OOB_FILL_NONE);
}

extern "C" void kernel_launch(void* const* d_in, const int* in_sizes, int n_in,
                              void* d_out, int out_size) {
    const float* q = (const float*)d_in[0];
    const float* p = (const float*)d_in[1];
    int np = in_sizes[1] / in_sizes[0];                    // = 8

    void* sym = nullptr;
    cudaDriverEntryPointQueryResult qres;
    cudaGetDriverEntryPoint("cuTensorMapEncodeTiled", &sym,
                            cudaEnableDefault, &qres);
    EncodeTiledFn enc = (EncodeTiledFn)sym;

    void *qh_ptr = nullptr, *ph_ptr = nullptr;
    cudaGetSymbolAddress(&qh_ptr, g_qh);
    cudaGetSymbolAddress(&ph_ptr, g_ph);

    CUtensorMap tmap_a, tmap_b;
    encode_map_f16(enc, &tmap_a, qh_ptr, B_DIM, MT);
    encode_map_f16(enc, &tmap_b, ph_ptr, P_DIM, NT);

    cudaFuncSetAttribute(fused_mma_kernel,
                         cudaFuncAttributeMaxDynamicSharedMemorySize, SMEM_TOTAL);

    int nsm = 148;
    cudaDeviceGetAttribute(&nsm, cudaDevAttrMultiProcessorCount, 0);
    int grid = (nsm < NUM_TILES) ? nsm : NUM_TILES;

    convert_kernel<<<(QF4 + PF4 + 255) / 256, 256>>>(q, p);
    target_kernel<<<B_DIM / 8, 256>>>(q, p, np);
    fused_mma_kernel<<<grid, 256, SMEM_TOTAL>>>(tmap_a, tmap_b);
    rowloss_kernel<<<B_DIM / 8, 256>>>();
    reduce_kernel<<<1, 1024>>>((float*)d_out);
}